// round 1
// baseline (speedup 1.0000x reference)
#include <cuda_runtime.h>
#include <cuda_bf16.h>
#include <cstdint>

// Problem constants
#define BB 2
#define LL 2048
#define DD 768
#define DI 1536
#define DS 16
#define DTR 48
#define KK 4
#define ROWS (BB*LL)            // 4096
#define DBC_W (DTR + 2*DS)      // 80

// ---------------- scratch (device globals; allocation-free) ----------------
__device__ float g_xn   [ROWS*DD];
__device__ float g_xflip[ROWS*DD];
__device__ float g_xz   [(size_t)ROWS*2*DI];
__device__ float g_xc   [(size_t)ROWS*DI];
__device__ float g_dbc  [(size_t)ROWS*DBC_W];
__device__ float g_dt   [(size_t)ROWS*DI];
__device__ float g_y    [(size_t)ROWS*DI];
__device__ float g_xf   [ROWS*DD];
__device__ float g_xbt  [ROWS*DD];
__device__ float g_cat  [(size_t)ROWS*2*DD];
__device__ float g_h    [ROWS*DD];
__device__ float g_hn   [ROWS*DD];
__device__ float g_ff1  [(size_t)ROWS*4*DD];

// ---------------- helpers ----------------
__device__ __forceinline__ float siluf(float x) {
    return x / (1.0f + __expf(-x));
}
__device__ __forceinline__ float geluf(float x) {
    // jax.nn.gelu (approximate=True, tanh form)
    float x3 = x * x * x;
    return 0.5f * x * (1.0f + tanhf(0.7978845608028654f * (x + 0.044715f * x3)));
}
__device__ __forceinline__ float softplusf(float x) {
    if (x > 20.0f) return x;
    return log1pf(__expf(x));
}

// ---------------- LayerNorm ----------------
__global__ void layernorm_kernel(const float* __restrict__ x,
                                 const float* __restrict__ g,
                                 const float* __restrict__ b,
                                 float* __restrict__ out) {
    int row = blockIdx.x;
    const float* xr = x + (size_t)row * DD;
    float s = 0.f, s2 = 0.f;
    for (int i = threadIdx.x; i < DD; i += blockDim.x) {
        float v = xr[i];
        s += v; s2 += v * v;
    }
    __shared__ float shm[2][33];
    #pragma unroll
    for (int off = 16; off; off >>= 1) {
        s  += __shfl_xor_sync(0xffffffffu, s,  off);
        s2 += __shfl_xor_sync(0xffffffffu, s2, off);
    }
    int lane = threadIdx.x & 31, w = threadIdx.x >> 5;
    if (lane == 0) { shm[0][w] = s; shm[1][w] = s2; }
    __syncthreads();
    int nw = blockDim.x >> 5;
    if (w == 0) {
        s  = (lane < nw) ? shm[0][lane] : 0.f;
        s2 = (lane < nw) ? shm[1][lane] : 0.f;
        #pragma unroll
        for (int off = 16; off; off >>= 1) {
            s  += __shfl_xor_sync(0xffffffffu, s,  off);
            s2 += __shfl_xor_sync(0xffffffffu, s2, off);
        }
        if (lane == 0) { shm[0][32] = s; shm[1][32] = s2; }
    }
    __syncthreads();
    float mu  = shm[0][32] * (1.0f / DD);
    float var = shm[1][32] * (1.0f / DD) - mu * mu;
    float inv = rsqrtf(var + 1e-5f);
    float* orow = out + (size_t)row * DD;
    for (int i = threadIdx.x; i < DD; i += blockDim.x)
        orow[i] = (xr[i] - mu) * inv * g[i] + b[i];
}

// ---------------- Tiled SGEMM: C[m,n] = act(sum_k A[m,k]*W[n,k] + bias[n]) + res[m,n] ----------------
#define BM 64
#define BN 64
#define BKK 16

template<int ACT>  // 0=none, 1=gelu, 2=softplus
__global__ __launch_bounds__(256)
void gemm_tn(const float* __restrict__ A, int lda,
             const float* __restrict__ W, int ldw,
             float* __restrict__ C, int ldc,
             int M, int N, int Kd,
             const float* __restrict__ bias,
             const float* __restrict__ res, int ldres) {
    __shared__ __align__(16) float As[BKK][BM];
    __shared__ __align__(16) float Ws[BKK][BN];
    int tid = threadIdx.x;
    int tx = tid & 15, ty = tid >> 4;
    int bm = blockIdx.y * BM, bn = blockIdx.x * BN;

    float acc[4][4] = {};
    for (int k0 = 0; k0 < Kd; k0 += BKK) {
        #pragma unroll
        for (int j = 0; j < 4; j++) {
            int i = tid + j * 256;       // 0..1023
            int r = i >> 4, c = i & 15;  // 64 rows x 16 k
            int gk = k0 + c;
            int gm = bm + r;
            As[c][r] = (gm < M && gk < Kd) ? A[(size_t)gm * lda + gk] : 0.f;
            int gn = bn + r;
            Ws[c][r] = (gn < N && gk < Kd) ? W[(size_t)gn * ldw + gk] : 0.f;
        }
        __syncthreads();
        #pragma unroll
        for (int k = 0; k < BKK; k++) {
            float4 a4 = *reinterpret_cast<const float4*>(&As[k][ty * 4]);
            float4 w4 = *reinterpret_cast<const float4*>(&Ws[k][tx * 4]);
            float av[4] = {a4.x, a4.y, a4.z, a4.w};
            float wv[4] = {w4.x, w4.y, w4.z, w4.w};
            #pragma unroll
            for (int i = 0; i < 4; i++)
                #pragma unroll
                for (int j = 0; j < 4; j++)
                    acc[i][j] += av[i] * wv[j];
        }
        __syncthreads();
    }
    #pragma unroll
    for (int i = 0; i < 4; i++) {
        int gm = bm + ty * 4 + i;
        if (gm >= M) continue;
        #pragma unroll
        for (int j = 0; j < 4; j++) {
            int gn = bn + tx * 4 + j;
            if (gn >= N) continue;
            float v = acc[i][j];
            if (bias) v += bias[gn];
            if (ACT == 1) v = geluf(v);
            else if (ACT == 2) v = softplusf(v);
            if (res) v += res[(size_t)gm * ldres + gn];
            C[(size_t)gm * ldc + gn] = v;
        }
    }
}

// ---------------- causal conv (K=4) + bias + silu ----------------
__global__ void conv_silu_kernel(const float* __restrict__ xz,
                                 const float* __restrict__ cw,
                                 const float* __restrict__ cb,
                                 float* __restrict__ out) {
    int idx = blockIdx.x * blockDim.x + threadIdx.x;
    if (idx >= ROWS * DI) return;
    int d = idx % DI;
    int t = (idx / DI) % LL;
    int b = idx / (DI * LL);
    float acc = cb[d];
    #pragma unroll
    for (int k = 0; k < KK; k++) {
        int tt = t - (KK - 1) + k;
        if (tt >= 0)
            acc += xz[((size_t)(b * LL + tt)) * (2 * DI) + d] * cw[d * KK + k];
    }
    out[idx] = siluf(acc);
}

// ---------------- selective scan + D skip + z-gating ----------------
// 16 lanes per (b,d) pair: lane s holds state h[b,d,s].
__global__ void scan_kernel(const float* __restrict__ dt,
                            const float* __restrict__ xc,
                            const float* __restrict__ dbc,
                            const float* __restrict__ xz,
                            const float* __restrict__ A_log,
                            const float* __restrict__ Dp,
                            float* __restrict__ y) {
    int gidx = blockIdx.x * (blockDim.x >> 4) + (threadIdx.x >> 4);
    int s = threadIdx.x & 15;
    int b = gidx / DI, d = gidx % DI;
    if (b >= BB) return;
    float Aval = -__expf(A_log[d * DS + s]);
    float Dv = Dp[d];
    float h = 0.f;
    for (int t = 0; t < LL; t++) {
        size_t row = (size_t)b * LL + t;
        float dtv = dt[row * DI + d];
        float xv  = xc[row * DI + d];
        float Bv  = dbc[row * DBC_W + DTR + s];
        float Cv  = dbc[row * DBC_W + DTR + DS + s];
        h = __expf(dtv * Aval) * h + dtv * xv * Bv;
        float part = h * Cv;
        #pragma unroll
        for (int off = 8; off; off >>= 1)
            part += __shfl_xor_sync(0xffffffffu, part, off);
        if (s == 0) {
            float zv = xz[row * (2 * DI) + DI + d];
            y[row * DI + d] = (part + xv * Dv) * siluf(zv);
        }
    }
}

// ---------------- flip along time ----------------
__global__ void flip_kernel(const float* __restrict__ in, float* __restrict__ out) {
    int idx = blockIdx.x * blockDim.x + threadIdx.x;
    if (idx >= ROWS * DD) return;
    int c = idx % DD;
    int t = (idx / DD) % LL;
    int b = idx / (DD * LL);
    out[idx] = in[((size_t)(b * LL + (LL - 1 - t))) * DD + c];
}

// ---------------- concat(xf, flip(xbt)) ----------------
__global__ void concat_kernel(const float* __restrict__ xf,
                              const float* __restrict__ xbt,
                              float* __restrict__ cat) {
    int idx = blockIdx.x * blockDim.x + threadIdx.x;
    if (idx >= ROWS * 2 * DD) return;
    int c = idx % (2 * DD);
    int t = (idx / (2 * DD)) % LL;
    int b = idx / (2 * DD * LL);
    float v;
    if (c < DD)
        v = xf[((size_t)(b * LL + t)) * DD + c];
    else
        v = xbt[((size_t)(b * LL + (LL - 1 - t))) * DD + (c - DD)];
    cat[idx] = v;
}

// ---------------- host side ----------------
static float* sym(const void* s) {
    void* p = nullptr;
    cudaGetSymbolAddress(&p, s);
    return (float*)p;
}

static void run_mamba(const float* xin,
                      const float* in_w, const float* conv_w, const float* conv_b,
                      const float* xproj_w, const float* dt_w, const float* dt_b,
                      const float* A_log, const float* Dp, const float* out_w,
                      float* out,
                      float* xz, float* xc, float* dbc, float* dt, float* y) {
    dim3 thr(256);
    // in_proj: [4096,768] x [3072,768]^T -> [4096,3072]
    gemm_tn<0><<<dim3((2 * DI + BN - 1) / BN, (ROWS + BM - 1) / BM), thr>>>(
        xin, DD, in_w, DD, xz, 2 * DI, ROWS, 2 * DI, DD, nullptr, nullptr, 0);
    // conv + silu
    conv_silu_kernel<<<(ROWS * DI + 255) / 256, 256>>>(xz, conv_w, conv_b, xc);
    // xproj: [4096,1536] x [80,1536]^T -> [4096,80]
    gemm_tn<0><<<dim3((DBC_W + BN - 1) / BN, (ROWS + BM - 1) / BM), thr>>>(
        xc, DI, xproj_w, DI, dbc, DBC_W, ROWS, DBC_W, DI, nullptr, nullptr, 0);
    // dt proj + softplus: [4096,48(ld 80)] x [1536,48]^T -> [4096,1536]
    gemm_tn<2><<<dim3((DI + BN - 1) / BN, (ROWS + BM - 1) / BM), thr>>>(
        dbc, DBC_W, dt_w, DTR, dt, DI, ROWS, DI, DTR, dt_b, nullptr, 0);
    // scan (fused D skip + silu(z) gating)
    scan_kernel<<<(BB * DI) / 16, 256>>>(dt, xc, dbc, xz, A_log, Dp, y);
    // out_proj: [4096,1536] x [768,1536]^T -> [4096,768]
    gemm_tn<0><<<dim3((DD + BN - 1) / BN, (ROWS + BM - 1) / BM), thr>>>(
        y, DI, out_w, DI, out, DD, ROWS, DD, DI, nullptr, nullptr, 0);
}

extern "C" void kernel_launch(void* const* d_in, const int* in_sizes, int n_in,
                              void* d_out, int out_size) {
    const float* x        = (const float*)d_in[0];
    const float* norm_g   = (const float*)d_in[1];
    const float* norm_b   = (const float*)d_in[2];
    const float* f_in_w   = (const float*)d_in[3];
    const float* f_conv_w = (const float*)d_in[4];
    const float* f_conv_b = (const float*)d_in[5];
    const float* f_xproj_w= (const float*)d_in[6];
    const float* f_dt_w   = (const float*)d_in[7];
    const float* f_dt_b   = (const float*)d_in[8];
    const float* f_A_log  = (const float*)d_in[9];
    const float* f_D      = (const float*)d_in[10];
    const float* f_out_w  = (const float*)d_in[11];
    const float* b_in_w   = (const float*)d_in[12];
    const float* b_conv_w = (const float*)d_in[13];
    const float* b_conv_b = (const float*)d_in[14];
    const float* b_xproj_w= (const float*)d_in[15];
    const float* b_dt_w   = (const float*)d_in[16];
    const float* b_dt_b   = (const float*)d_in[17];
    const float* b_A_log  = (const float*)d_in[18];
    const float* b_D      = (const float*)d_in[19];
    const float* b_out_w  = (const float*)d_in[20];
    const float* mix_w    = (const float*)d_in[21];
    const float* mix_b    = (const float*)d_in[22];
    const float* ffn_w1   = (const float*)d_in[23];
    const float* ffn_b1   = (const float*)d_in[24];
    const float* ffn_w2   = (const float*)d_in[25];
    const float* ffn_b2   = (const float*)d_in[26];
    const float* ffn_norm_g = (const float*)d_in[27];
    const float* ffn_norm_b = (const float*)d_in[28];

    float* xn    = sym(g_xn);
    float* xflip = sym(g_xflip);
    float* xz    = sym(g_xz);
    float* xc    = sym(g_xc);
    float* dbc   = sym(g_dbc);
    float* dt    = sym(g_dt);
    float* y     = sym(g_y);
    float* xf    = sym(g_xf);
    float* xbt   = sym(g_xbt);
    float* cat   = sym(g_cat);
    float* h     = sym(g_h);
    float* hn    = sym(g_hn);
    float* ff1   = sym(g_ff1);
    float* out   = (float*)d_out;

    dim3 thr(256);

    // 1) layernorm
    layernorm_kernel<<<ROWS, 256>>>(x, norm_g, norm_b, xn);

    // 2) forward mamba
    run_mamba(xn, f_in_w, f_conv_w, f_conv_b, f_xproj_w, f_dt_w, f_dt_b,
              f_A_log, f_D, f_out_w, xf, xz, xc, dbc, dt, y);

    // 3) backward mamba on time-flipped input
    flip_kernel<<<(ROWS * DD + 255) / 256, 256>>>(xn, xflip);
    run_mamba(xflip, b_in_w, b_conv_w, b_conv_b, b_xproj_w, b_dt_w, b_dt_b,
              b_A_log, b_D, b_out_w, xbt, xz, xc, dbc, dt, y);

    // 4) concat (un-flips backward branch)
    concat_kernel<<<(ROWS * 2 * DD + 255) / 256, 256>>>(xf, xbt, cat);

    // 5) mix + bias + residual -> h
    gemm_tn<0><<<dim3((DD + BN - 1) / BN, (ROWS + BM - 1) / BM), thr>>>(
        cat, 2 * DD, mix_w, 2 * DD, h, DD, ROWS, DD, 2 * DD, mix_b, x, DD);

    // 6) layernorm 2
    layernorm_kernel<<<ROWS, 256>>>(h, ffn_norm_g, ffn_norm_b, hn);

    // 7) FFN1 + bias + gelu
    gemm_tn<1><<<dim3((4 * DD + BN - 1) / BN, (ROWS + BM - 1) / BM), thr>>>(
        hn, DD, ffn_w1, DD, ff1, 4 * DD, ROWS, 4 * DD, DD, ffn_b1, nullptr, 0);

    // 8) FFN2 + bias + residual(h) -> out
    gemm_tn<0><<<dim3((DD + BN - 1) / BN, (ROWS + BM - 1) / BM), thr>>>(
        ff1, 4 * DD, ffn_w2, 4 * DD, out, DD, ROWS, DD, 4 * DD, ffn_b2, h, DD);
}

// round 3
// speedup vs baseline: 3.2040x; 3.2040x over previous
#include <cuda_runtime.h>
#include <cuda_bf16.h>
#include <cstdint>

// Problem constants
#define BB 2
#define LL 2048
#define DD 768
#define DI 1536
#define DS 16
#define DTR 48
#define KK 4
#define ROWS (BB*LL)            // 4096
#define DBC_W (DTR + 2*DS)      // 80

// ---------------- scratch (device globals; allocation-free) ----------------
__device__ float g_xn   [ROWS*DD];
__device__ float g_xflip[ROWS*DD];
__device__ float g_xz   [(size_t)ROWS*2*DI];
__device__ float g_xc   [(size_t)ROWS*DI];
__device__ float g_dbc  [(size_t)ROWS*DBC_W];
__device__ float g_dt   [(size_t)ROWS*DI];
__device__ float g_y    [(size_t)ROWS*DI];
__device__ float g_xf   [ROWS*DD];
__device__ float g_xbt  [ROWS*DD];
__device__ float g_cat  [(size_t)ROWS*2*DD];
__device__ float g_h    [ROWS*DD];
__device__ float g_hn   [ROWS*DD];
__device__ float g_ff1  [(size_t)ROWS*4*DD];

// ---------------- helpers ----------------
__device__ __forceinline__ float siluf(float x) {
    return x / (1.0f + __expf(-x));
}
__device__ __forceinline__ float geluf(float x) {
    float x3 = x * x * x;
    return 0.5f * x * (1.0f + tanhf(0.7978845608028654f * (x + 0.044715f * x3)));
}
__device__ __forceinline__ float softplusf(float x) {
    if (x > 20.0f) return x;
    return log1pf(__expf(x));
}

__device__ __forceinline__ uint32_t smem_u32(const void* p) {
    uint32_t a;
    asm("{ .reg .u64 t; cvta.to.shared.u64 t, %1; cvt.u32.u64 %0, t; }" : "=r"(a) : "l"(p));
    return a;
}
__device__ __forceinline__ void cpa16(uint32_t dst, const float* src, bool v) {
    int sz = v ? 16 : 0;
    asm volatile("cp.async.cg.shared.global [%0], [%1], 16, %2;"
        :: "r"(dst), "l"(src), "r"(sz) : "memory");
}
#define CP_COMMIT() asm volatile("cp.async.commit_group;" ::: "memory")
#define CP_WAIT(n)  asm volatile("cp.async.wait_group %0;" :: "n"(n) : "memory")

__device__ __forceinline__ uint32_t to_tf32(float x) {
    uint32_t u;
    asm("cvt.rna.tf32.f32 %0, %1;" : "=r"(u) : "f"(x));
    return u;
}
__device__ __forceinline__ void mma_tf32(float* d, const uint32_t* a, const uint32_t* b) {
    asm volatile("mma.sync.aligned.m16n8k8.row.col.f32.tf32.tf32.f32 "
                 "{%0,%1,%2,%3}, {%4,%5,%6,%7}, {%8,%9}, {%0,%1,%2,%3};"
                 : "+f"(d[0]), "+f"(d[1]), "+f"(d[2]), "+f"(d[3])
                 : "r"(a[0]), "r"(a[1]), "r"(a[2]), "r"(a[3]),
                   "r"(b[0]), "r"(b[1]));
}

// ================= tf32 mma.sync GEMM =================
// C[m,n] = act(sum_k A[m,k]*W[n,k] + bias[n]) + res[m,n]
// Tile 128x128x32, 8 warps (2x4), warp tile 64x32, double-buffered cp.async.
#define GBM 128
#define GBN 128
#define GBK 32
#define GAS 36                 // padded k-stride (floats)
#define BUFA_BYTES (GBM*GAS*4) // 18432
#define SMEM_GEMM (4*BUFA_BYTES)  // 73728: A[2] + B[2]

template<int ACT>  // 0=none, 1=gelu, 2=softplus
__global__ __launch_bounds__(256)
void tgemm(const float* __restrict__ A, int lda,
           const float* __restrict__ W, int ldw,
           float* __restrict__ C, int ldc,
           int M, int N, int Kd,
           const float* __restrict__ bias,
           const float* __restrict__ res, int ldres) {
    extern __shared__ float smf[];
    float* As = smf;                    // [2][GBM][GAS]
    float* Bs = smf + 2 * GBM * GAS;    // [2][GBN][GAS]
    uint32_t sA = smem_u32(As);
    uint32_t sB = smem_u32(Bs);

    int tid = threadIdx.x;
    int lane = tid & 31, wid = tid >> 5;
    int bm = blockIdx.y * GBM, bn = blockIdx.x * GBN;
    int wm = (wid & 1) * 64, wn = (wid >> 1) * 32;
    int g = lane >> 2, l = lane & 3;

    float acc[4][4][4];
    #pragma unroll
    for (int f = 0; f < 4; f++)
        #pragma unroll
        for (int j = 0; j < 4; j++)
            #pragma unroll
            for (int c = 0; c < 4; c++) acc[f][j][c] = 0.f;

    const int lr = tid >> 3;        // 0..31
    const int lc = (tid & 7) * 4;   // 0,4,..,28

    auto load_stage = [&](int buf, int kt) {
        int k = kt * GBK + lc;
        bool kok = (k < Kd);
        int kk = kok ? k : 0;
        #pragma unroll
        for (int j = 0; j < 4; j++) {
            int r = lr + j * 32;
            int gm = bm + r;
            bool v = kok && (gm < M);
            cpa16(sA + buf * BUFA_BYTES + (r * GAS + lc) * 4,
                  A + (size_t)(v ? gm : bm) * lda + kk, v);
        }
        #pragma unroll
        for (int j = 0; j < 4; j++) {
            int r = lr + j * 32;
            int gn = bn + r;
            bool v = kok && (gn < N);
            cpa16(sB + buf * BUFA_BYTES + (r * GAS + lc) * 4,
                  W + (size_t)(v ? gn : 0) * ldw + kk, v);
        }
        CP_COMMIT();
    };

    const int NT = (Kd + GBK - 1) / GBK;
    load_stage(0, 0);

    for (int kt = 0; kt < NT; kt++) {
        int buf = kt & 1;
        if (kt + 1 < NT) {
            load_stage(buf ^ 1, kt + 1);
            CP_WAIT(1);
        } else {
            CP_WAIT(0);
        }
        __syncthreads();

        const float* as = As + buf * GBM * GAS;
        const float* bs = Bs + buf * GBN * GAS;
        #pragma unroll
        for (int k0 = 0; k0 < GBK; k0 += 8) {
            uint32_t af[4][4], bf[4][2];
            #pragma unroll
            for (int f = 0; f < 4; f++) {
                int r0 = wm + f * 16 + g;
                af[f][0] = to_tf32(as[r0 * GAS + k0 + l]);
                af[f][1] = to_tf32(as[(r0 + 8) * GAS + k0 + l]);
                af[f][2] = to_tf32(as[r0 * GAS + k0 + l + 4]);
                af[f][3] = to_tf32(as[(r0 + 8) * GAS + k0 + l + 4]);
            }
            #pragma unroll
            for (int j = 0; j < 4; j++) {
                int c0 = wn + j * 8 + g;
                bf[j][0] = to_tf32(bs[c0 * GAS + k0 + l]);
                bf[j][1] = to_tf32(bs[c0 * GAS + k0 + l + 4]);
            }
            #pragma unroll
            for (int f = 0; f < 4; f++)
                #pragma unroll
                for (int j = 0; j < 4; j++)
                    mma_tf32(acc[f][j], af[f], bf[j]);
        }
        __syncthreads();
    }

    // epilogue: c0:(g,2l) c1:(g,2l+1) c2:(g+8,2l) c3:(g+8,2l+1)
    #pragma unroll
    for (int f = 0; f < 4; f++) {
        int gm0 = bm + wm + f * 16 + g;
        #pragma unroll
        for (int j = 0; j < 4; j++) {
            int gn = bn + wn + j * 8 + 2 * l;
            if (gn >= N) continue;
            bool n1 = (gn + 1 < N);
            float b0 = bias ? bias[gn] : 0.f;
            float b1 = (bias && n1) ? bias[gn + 1] : 0.f;
            #pragma unroll
            for (int half = 0; half < 2; half++) {
                int gm = gm0 + half * 8;
                if (gm >= M) continue;
                float v0 = acc[f][j][half * 2 + 0] + b0;
                float v1 = acc[f][j][half * 2 + 1] + b1;
                if (ACT == 1) { v0 = geluf(v0); v1 = geluf(v1); }
                else if (ACT == 2) { v0 = softplusf(v0); v1 = softplusf(v1); }
                if (res) {
                    v0 += res[(size_t)gm * ldres + gn];
                    if (n1) v1 += res[(size_t)gm * ldres + gn + 1];
                }
                C[(size_t)gm * ldc + gn] = v0;
                if (n1) C[(size_t)gm * ldc + gn + 1] = v1;
            }
        }
    }
}

// ---------------- LayerNorm ----------------
__global__ void layernorm_kernel(const float* __restrict__ x,
                                 const float* __restrict__ g,
                                 const float* __restrict__ b,
                                 float* __restrict__ out) {
    int row = blockIdx.x;
    const float* xr = x + (size_t)row * DD;
    float s = 0.f, s2 = 0.f;
    for (int i = threadIdx.x; i < DD; i += blockDim.x) {
        float v = xr[i];
        s += v; s2 += v * v;
    }
    __shared__ float shm[2][33];
    #pragma unroll
    for (int off = 16; off; off >>= 1) {
        s  += __shfl_xor_sync(0xffffffffu, s,  off);
        s2 += __shfl_xor_sync(0xffffffffu, s2, off);
    }
    int lane = threadIdx.x & 31, w = threadIdx.x >> 5;
    if (lane == 0) { shm[0][w] = s; shm[1][w] = s2; }
    __syncthreads();
    int nw = blockDim.x >> 5;
    if (w == 0) {
        s  = (lane < nw) ? shm[0][lane] : 0.f;
        s2 = (lane < nw) ? shm[1][lane] : 0.f;
        #pragma unroll
        for (int off = 16; off; off >>= 1) {
            s  += __shfl_xor_sync(0xffffffffu, s,  off);
            s2 += __shfl_xor_sync(0xffffffffu, s2, off);
        }
        if (lane == 0) { shm[0][32] = s; shm[1][32] = s2; }
    }
    __syncthreads();
    float mu  = shm[0][32] * (1.0f / DD);
    float var = shm[1][32] * (1.0f / DD) - mu * mu;
    float inv = rsqrtf(var + 1e-5f);
    float* orow = out + (size_t)row * DD;
    for (int i = threadIdx.x; i < DD; i += blockDim.x)
        orow[i] = (xr[i] - mu) * inv * g[i] + b[i];
}

// ---------------- causal conv (K=4) + bias + silu ----------------
__global__ void conv_silu_kernel(const float* __restrict__ xz,
                                 const float* __restrict__ cw,
                                 const float* __restrict__ cb,
                                 float* __restrict__ out) {
    int idx = blockIdx.x * blockDim.x + threadIdx.x;
    if (idx >= ROWS * DI) return;
    int d = idx % DI;
    int t = (idx / DI) % LL;
    int b = idx / (DI * LL);
    float acc = cb[d];
    #pragma unroll
    for (int k = 0; k < KK; k++) {
        int tt = t - (KK - 1) + k;
        if (tt >= 0)
            acc += xz[((size_t)(b * LL + tt)) * (2 * DI) + d] * cw[d * KK + k];
    }
    out[idx] = siluf(acc);
}

// ---------------- selective scan + D skip + z-gating (prefetched) ----------------
__global__ void scan_kernel(const float* __restrict__ dt,
                            const float* __restrict__ xc,
                            const float* __restrict__ dbc,
                            const float* __restrict__ xz,
                            const float* __restrict__ A_log,
                            const float* __restrict__ Dp,
                            float* __restrict__ y) {
    int gidx = blockIdx.x * (blockDim.x >> 4) + (threadIdx.x >> 4);
    int s = threadIdx.x & 15;
    int b = gidx / DI, d = gidx % DI;
    if (b >= BB) return;
    float Aval = -__expf(A_log[d * DS + s]);
    float Dv = Dp[d];
    float h = 0.f;

    size_t row0 = (size_t)b * LL;
    float c_dt = dt[row0 * DI + d];
    float c_x  = xc[row0 * DI + d];
    float c_B  = dbc[row0 * DBC_W + DTR + s];
    float c_C  = dbc[row0 * DBC_W + DTR + DS + s];
    float c_z  = xz[row0 * (2 * DI) + DI + d];

    for (int t = 0; t < LL; t++) {
        float n_dt = 0.f, n_x = 0.f, n_B = 0.f, n_C = 0.f, n_z = 0.f;
        if (t + 1 < LL) {
            size_t rn = row0 + t + 1;
            n_dt = dt[rn * DI + d];
            n_x  = xc[rn * DI + d];
            n_B  = dbc[rn * DBC_W + DTR + s];
            n_C  = dbc[rn * DBC_W + DTR + DS + s];
            n_z  = xz[rn * (2 * DI) + DI + d];
        }
        h = __expf(c_dt * Aval) * h + c_dt * c_x * c_B;
        float part = h * c_C;
        #pragma unroll
        for (int off = 8; off; off >>= 1)
            part += __shfl_xor_sync(0xffffffffu, part, off);
        if (s == 0) {
            size_t row = row0 + t;
            y[row * DI + d] = (part + c_x * Dv) * siluf(c_z);
        }
        c_dt = n_dt; c_x = n_x; c_B = n_B; c_C = n_C; c_z = n_z;
    }
}

// ---------------- flip along time ----------------
__global__ void flip_kernel(const float* __restrict__ in, float* __restrict__ out) {
    int idx = blockIdx.x * blockDim.x + threadIdx.x;
    if (idx >= ROWS * DD) return;
    int c = idx % DD;
    int t = (idx / DD) % LL;
    int b = idx / (DD * LL);
    out[idx] = in[((size_t)(b * LL + (LL - 1 - t))) * DD + c];
}

// ---------------- concat(xf, flip(xbt)) ----------------
__global__ void concat_kernel(const float* __restrict__ xf,
                              const float* __restrict__ xbt,
                              float* __restrict__ cat) {
    int idx = blockIdx.x * blockDim.x + threadIdx.x;
    if (idx >= ROWS * 2 * DD) return;
    int c = idx % (2 * DD);
    int t = (idx / (2 * DD)) % LL;
    int b = idx / (2 * DD * LL);
    float v;
    if (c < DD)
        v = xf[((size_t)(b * LL + t)) * DD + c];
    else
        v = xbt[((size_t)(b * LL + (LL - 1 - t))) * DD + (c - DD)];
    cat[idx] = v;
}

// ---------------- host side ----------------
static float* sym(const void* s) {
    void* p = nullptr;
    cudaGetSymbolAddress(&p, s);
    return (float*)p;
}

template<int ACT>
static void launch_tgemm(const float* A, int lda, const float* W, int ldw,
                         float* C, int ldc, int M, int N, int Kd,
                         const float* bias, const float* res, int ldres) {
    cudaFuncSetAttribute(tgemm<ACT>, cudaFuncAttributeMaxDynamicSharedMemorySize, SMEM_GEMM);
    dim3 grid((N + GBN - 1) / GBN, (M + GBM - 1) / GBM);
    tgemm<ACT><<<grid, 256, SMEM_GEMM>>>(A, lda, W, ldw, C, ldc, M, N, Kd, bias, res, ldres);
}

static void run_mamba(const float* xin,
                      const float* in_w, const float* conv_w, const float* conv_b,
                      const float* xproj_w, const float* dt_w, const float* dt_b,
                      const float* A_log, const float* Dp, const float* out_w,
                      float* out,
                      float* xz, float* xc, float* dbc, float* dt, float* y) {
    // in_proj: [4096,768] x [3072,768]^T -> [4096,3072]
    launch_tgemm<0>(xin, DD, in_w, DD, xz, 2 * DI, ROWS, 2 * DI, DD, nullptr, nullptr, 0);
    // conv + silu
    conv_silu_kernel<<<(ROWS * DI + 255) / 256, 256>>>(xz, conv_w, conv_b, xc);
    // xproj: [4096,1536] x [80,1536]^T -> [4096,80]
    launch_tgemm<0>(xc, DI, xproj_w, DI, dbc, DBC_W, ROWS, DBC_W, DI, nullptr, nullptr, 0);
    // dt proj + softplus: [4096,48(ld 80)] x [1536,48]^T -> [4096,1536]
    launch_tgemm<2>(dbc, DBC_W, dt_w, DTR, dt, DI, ROWS, DI, DTR, dt_b, nullptr, 0);
    // scan (fused D skip + silu(z) gating)
    scan_kernel<<<(BB * DI) / 16, 256>>>(dt, xc, dbc, xz, A_log, Dp, y);
    // out_proj: [4096,1536] x [768,1536]^T -> [4096,768]
    launch_tgemm<0>(y, DI, out_w, DI, out, DD, ROWS, DD, DI, nullptr, nullptr, 0);
}

extern "C" void kernel_launch(void* const* d_in, const int* in_sizes, int n_in,
                              void* d_out, int out_size) {
    const float* x        = (const float*)d_in[0];
    const float* norm_g   = (const float*)d_in[1];
    const float* norm_b   = (const float*)d_in[2];
    const float* f_in_w   = (const float*)d_in[3];
    const float* f_conv_w = (const float*)d_in[4];
    const float* f_conv_b = (const float*)d_in[5];
    const float* f_xproj_w= (const float*)d_in[6];
    const float* f_dt_w   = (const float*)d_in[7];
    const float* f_dt_b   = (const float*)d_in[8];
    const float* f_A_log  = (const float*)d_in[9];
    const float* f_D      = (const float*)d_in[10];
    const float* f_out_w  = (const float*)d_in[11];
    const float* b_in_w   = (const float*)d_in[12];
    const float* b_conv_w = (const float*)d_in[13];
    const float* b_conv_b = (const float*)d_in[14];
    const float* b_xproj_w= (const float*)d_in[15];
    const float* b_dt_w   = (const float*)d_in[16];
    const float* b_dt_b   = (const float*)d_in[17];
    const float* b_A_log  = (const float*)d_in[18];
    const float* b_D      = (const float*)d_in[19];
    const float* b_out_w  = (const float*)d_in[20];
    const float* mix_w    = (const float*)d_in[21];
    const float* mix_b    = (const float*)d_in[22];
    const float* ffn_w1   = (const float*)d_in[23];
    const float* ffn_b1   = (const float*)d_in[24];
    const float* ffn_w2   = (const float*)d_in[25];
    const float* ffn_b2   = (const float*)d_in[26];
    const float* ffn_norm_g = (const float*)d_in[27];
    const float* ffn_norm_b = (const float*)d_in[28];

    float* xn    = sym(g_xn);
    float* xflip = sym(g_xflip);
    float* xz    = sym(g_xz);
    float* xc    = sym(g_xc);
    float* dbc   = sym(g_dbc);
    float* dt    = sym(g_dt);
    float* y     = sym(g_y);
    float* xf    = sym(g_xf);
    float* xbt   = sym(g_xbt);
    float* cat   = sym(g_cat);
    float* h     = sym(g_h);
    float* hn    = sym(g_hn);
    float* ff1   = sym(g_ff1);
    float* out   = (float*)d_out;

    // 1) layernorm
    layernorm_kernel<<<ROWS, 256>>>(x, norm_g, norm_b, xn);

    // 2) forward mamba
    run_mamba(xn, f_in_w, f_conv_w, f_conv_b, f_xproj_w, f_dt_w, f_dt_b,
              f_A_log, f_D, f_out_w, xf, xz, xc, dbc, dt, y);

    // 3) backward mamba on time-flipped input
    flip_kernel<<<(ROWS * DD + 255) / 256, 256>>>(xn, xflip);
    run_mamba(xflip, b_in_w, b_conv_w, b_conv_b, b_xproj_w, b_dt_w, b_dt_b,
              b_A_log, b_D, b_out_w, xbt, xz, xc, dbc, dt, y);

    // 4) concat (un-flips backward branch)
    concat_kernel<<<(ROWS * 2 * DD + 255) / 256, 256>>>(xf, xbt, cat);

    // 5) mix + bias + residual -> h
    launch_tgemm<0>(cat, 2 * DD, mix_w, 2 * DD, h, DD, ROWS, DD, 2 * DD, mix_b, x, DD);

    // 6) layernorm 2
    layernorm_kernel<<<ROWS, 256>>>(h, ffn_norm_g, ffn_norm_b, hn);

    // 7) FFN1 + bias + gelu
    launch_tgemm<1>(hn, DD, ffn_w1, DD, ff1, 4 * DD, ROWS, 4 * DD, DD, ffn_b1, nullptr, 0);

    // 8) FFN2 + bias + residual(h) -> out
    launch_tgemm<0>(ff1, 4 * DD, ffn_w2, 4 * DD, out, DD, ROWS, DD, 4 * DD, ffn_b2, h, DD);
}

// round 4
// speedup vs baseline: 3.9017x; 1.2178x over previous
#include <cuda_runtime.h>
#include <cuda_bf16.h>
#include <cstdint>

// Problem constants
#define BB 2
#define LL 2048
#define DD 768
#define DI 1536
#define DS 16
#define DTR 48
#define KK 4
#define ROWS (BB*LL)            // 4096
#define DBC_W (DTR + 2*DS)      // 80

// ---------------- scratch (device globals; allocation-free) ----------------
// separate buffers per branch so fwd/bwd can run concurrently
__device__ float g_xn   [ROWS*DD];
__device__ float g_xz_f [(size_t)ROWS*2*DI];
__device__ float g_xc_f [(size_t)ROWS*DI];
__device__ float g_dbc_f[(size_t)ROWS*DBC_W];
__device__ float g_dt_f [(size_t)ROWS*DI];
__device__ float g_y_f  [(size_t)ROWS*DI];
__device__ float g_xz_b [(size_t)ROWS*2*DI];
__device__ float g_xc_b [(size_t)ROWS*DI];
__device__ float g_dbc_b[(size_t)ROWS*DBC_W];
__device__ float g_dt_b [(size_t)ROWS*DI];
__device__ float g_y_b  [(size_t)ROWS*DI];
__device__ float g_xf   [ROWS*DD];
__device__ float g_xbt  [ROWS*DD];
__device__ float g_cat  [(size_t)ROWS*2*DD];
__device__ float g_h    [ROWS*DD];
__device__ float g_hn   [ROWS*DD];
__device__ float g_ff1  [(size_t)ROWS*4*DD];

// ---------------- helpers ----------------
__device__ __forceinline__ float siluf(float x) {
    return x / (1.0f + __expf(-x));
}
__device__ __forceinline__ float geluf(float x) {
    float x3 = x * x * x;
    return 0.5f * x * (1.0f + tanhf(0.7978845608028654f * (x + 0.044715f * x3)));
}
__device__ __forceinline__ float softplusf(float x) {
    if (x > 20.0f) return x;
    return log1pf(__expf(x));
}

__device__ __forceinline__ void cpa16(uint32_t dst, const float* src, bool v) {
    int sz = v ? 16 : 0;
    asm volatile("cp.async.cg.shared.global [%0], [%1], 16, %2;"
        :: "r"(dst), "l"(src), "r"(sz) : "memory");
}
#define CP_COMMIT() asm volatile("cp.async.commit_group;" ::: "memory")
#define CP_WAIT(n)  asm volatile("cp.async.wait_group %0;" :: "n"(n) : "memory")

__device__ __forceinline__ uint32_t smem_u32(const void* p) {
    uint32_t a;
    asm("{ .reg .u64 t; cvta.to.shared.u64 t, %1; cvt.u32.u64 %0, t; }" : "=r"(a) : "l"(p));
    return a;
}
__device__ __forceinline__ void mma_tf32(float* d, const uint32_t* a, const uint32_t* b) {
    asm volatile("mma.sync.aligned.m16n8k8.row.col.f32.tf32.tf32.f32 "
                 "{%0,%1,%2,%3}, {%4,%5,%6,%7}, {%8,%9}, {%0,%1,%2,%3};"
                 : "+f"(d[0]), "+f"(d[1]), "+f"(d[2]), "+f"(d[3])
                 : "r"(a[0]), "r"(a[1]), "r"(a[2]), "r"(a[3]),
                   "r"(b[0]), "r"(b[1]));
}

// ================= tf32 mma.sync GEMM =================
// C[m,n] = act(sum_k A[m,k]*W[n,k] + bias[n]) + res[m,n]
// Tile 128x128x32, 8 warps (2x4), warp tile 64x32, double-buffered cp.async.
// FLIPA: A rows are read time-reversed within each batch (t -> LL-1-t).
#define GBM 128
#define GBN 128
#define GBK 32
#define GAS 36                 // padded k-stride (floats)
#define BUFA_BYTES (GBM*GAS*4) // 18432
#define SMEM_GEMM (4*BUFA_BYTES)  // 73728: A[2] + B[2]

template<int ACT, bool FLIPA>  // ACT: 0=none, 1=gelu, 2=softplus
__global__ __launch_bounds__(256, 2)
void tgemm(const float* __restrict__ A, int lda,
           const float* __restrict__ W, int ldw,
           float* __restrict__ C, int ldc,
           int M, int N, int Kd,
           const float* __restrict__ bias,
           const float* __restrict__ res, int ldres) {
    extern __shared__ float smf[];
    float* As = smf;                    // [2][GBM][GAS]
    float* Bs = smf + 2 * GBM * GAS;    // [2][GBN][GAS]
    uint32_t sA = smem_u32(As);
    uint32_t sB = smem_u32(Bs);

    int tid = threadIdx.x;
    int lane = tid & 31, wid = tid >> 5;
    int bm = blockIdx.y * GBM, bn = blockIdx.x * GBN;
    int wm = (wid & 1) * 64, wn = (wid >> 1) * 32;
    int g = lane >> 2, l = lane & 3;

    float acc[4][4][4];
    #pragma unroll
    for (int f = 0; f < 4; f++)
        #pragma unroll
        for (int j = 0; j < 4; j++)
            #pragma unroll
            for (int c = 0; c < 4; c++) acc[f][j][c] = 0.f;

    const int lr = tid >> 3;        // 0..31
    const int lc = (tid & 7) * 4;   // 0,4,..,28

    auto load_stage = [&](int buf, int kt) {
        int k = kt * GBK + lc;
        bool kok = (k < Kd);
        int kk = kok ? k : 0;
        #pragma unroll
        for (int j = 0; j < 4; j++) {
            int r = lr + j * 32;
            int gm = bm + r;
            bool v = kok && (gm < M);
            int gsrc = gm;
            if (FLIPA) gsrc = (gm & ~(LL - 1)) + (LL - 1 - (gm & (LL - 1)));
            cpa16(sA + buf * BUFA_BYTES + (r * GAS + lc) * 4,
                  A + (size_t)(v ? gsrc : 0) * lda + kk, v);
        }
        #pragma unroll
        for (int j = 0; j < 4; j++) {
            int r = lr + j * 32;
            int gn = bn + r;
            bool v = kok && (gn < N);
            cpa16(sB + buf * BUFA_BYTES + (r * GAS + lc) * 4,
                  W + (size_t)(v ? gn : 0) * ldw + kk, v);
        }
        CP_COMMIT();
    };

    const int NT = (Kd + GBK - 1) / GBK;
    load_stage(0, 0);

    for (int kt = 0; kt < NT; kt++) {
        int buf = kt & 1;
        if (kt + 1 < NT) {
            load_stage(buf ^ 1, kt + 1);
            CP_WAIT(1);
        } else {
            CP_WAIT(0);
        }
        __syncthreads();

        const uint32_t* as = (const uint32_t*)(As + buf * GBM * GAS);
        const uint32_t* bs = (const uint32_t*)(Bs + buf * GBN * GAS);
        #pragma unroll
        for (int k0 = 0; k0 < GBK; k0 += 8) {
            uint32_t af[4][4], bf[4][2];
            #pragma unroll
            for (int f = 0; f < 4; f++) {
                int r0 = wm + f * 16 + g;
                af[f][0] = as[r0 * GAS + k0 + l];
                af[f][1] = as[(r0 + 8) * GAS + k0 + l];
                af[f][2] = as[r0 * GAS + k0 + l + 4];
                af[f][3] = as[(r0 + 8) * GAS + k0 + l + 4];
            }
            #pragma unroll
            for (int j = 0; j < 4; j++) {
                int c0 = wn + j * 8 + g;
                bf[j][0] = bs[c0 * GAS + k0 + l];
                bf[j][1] = bs[c0 * GAS + k0 + l + 4];
            }
            #pragma unroll
            for (int f = 0; f < 4; f++)
                #pragma unroll
                for (int j = 0; j < 4; j++)
                    mma_tf32(acc[f][j], af[f], bf[j]);
        }
        __syncthreads();
    }

    // epilogue: c0:(g,2l) c1:(g,2l+1) c2:(g+8,2l) c3:(g+8,2l+1)
    #pragma unroll
    for (int f = 0; f < 4; f++) {
        int gm0 = bm + wm + f * 16 + g;
        #pragma unroll
        for (int j = 0; j < 4; j++) {
            int gn = bn + wn + j * 8 + 2 * l;
            if (gn >= N) continue;
            bool n1 = (gn + 1 < N);
            float b0 = bias ? bias[gn] : 0.f;
            float b1 = (bias && n1) ? bias[gn + 1] : 0.f;
            #pragma unroll
            for (int half = 0; half < 2; half++) {
                int gm = gm0 + half * 8;
                if (gm >= M) continue;
                float v0 = acc[f][j][half * 2 + 0] + b0;
                float v1 = acc[f][j][half * 2 + 1] + b1;
                if (ACT == 1) { v0 = geluf(v0); v1 = geluf(v1); }
                else if (ACT == 2) { v0 = softplusf(v0); v1 = softplusf(v1); }
                if (res) {
                    v0 += res[(size_t)gm * ldres + gn];
                    if (n1) v1 += res[(size_t)gm * ldres + gn + 1];
                }
                C[(size_t)gm * ldc + gn] = v0;
                if (n1) C[(size_t)gm * ldc + gn + 1] = v1;
            }
        }
    }
}

// ---------------- LayerNorm ----------------
__global__ void layernorm_kernel(const float* __restrict__ x,
                                 const float* __restrict__ g,
                                 const float* __restrict__ b,
                                 float* __restrict__ out) {
    int row = blockIdx.x;
    const float* xr = x + (size_t)row * DD;
    float s = 0.f, s2 = 0.f;
    for (int i = threadIdx.x; i < DD; i += blockDim.x) {
        float v = xr[i];
        s += v; s2 += v * v;
    }
    __shared__ float shm[2][33];
    #pragma unroll
    for (int off = 16; off; off >>= 1) {
        s  += __shfl_xor_sync(0xffffffffu, s,  off);
        s2 += __shfl_xor_sync(0xffffffffu, s2, off);
    }
    int lane = threadIdx.x & 31, w = threadIdx.x >> 5;
    if (lane == 0) { shm[0][w] = s; shm[1][w] = s2; }
    __syncthreads();
    int nw = blockDim.x >> 5;
    if (w == 0) {
        s  = (lane < nw) ? shm[0][lane] : 0.f;
        s2 = (lane < nw) ? shm[1][lane] : 0.f;
        #pragma unroll
        for (int off = 16; off; off >>= 1) {
            s  += __shfl_xor_sync(0xffffffffu, s,  off);
            s2 += __shfl_xor_sync(0xffffffffu, s2, off);
        }
        if (lane == 0) { shm[0][32] = s; shm[1][32] = s2; }
    }
    __syncthreads();
    float mu  = shm[0][32] * (1.0f / DD);
    float var = shm[1][32] * (1.0f / DD) - mu * mu;
    float inv = rsqrtf(var + 1e-5f);
    float* orow = out + (size_t)row * DD;
    for (int i = threadIdx.x; i < DD; i += blockDim.x)
        orow[i] = (xr[i] - mu) * inv * g[i] + b[i];
}

// ---------------- causal conv (K=4) + bias + silu ----------------
__global__ void conv_silu_kernel(const float* __restrict__ xz,
                                 const float* __restrict__ cw,
                                 const float* __restrict__ cb,
                                 float* __restrict__ out) {
    int idx = blockIdx.x * blockDim.x + threadIdx.x;
    if (idx >= ROWS * DI) return;
    int d = idx % DI;
    int t = (idx / DI) % LL;
    int b = idx / (DI * LL);
    float acc = cb[d];
    #pragma unroll
    for (int k = 0; k < KK; k++) {
        int tt = t - (KK - 1) + k;
        if (tt >= 0)
            acc += xz[((size_t)(b * LL + tt)) * (2 * DI) + d] * cw[d * KK + k];
    }
    out[idx] = siluf(acc);
}

// ---------------- selective scan + D skip + z-gating (prefetched) ----------------
__global__ void scan_kernel(const float* __restrict__ dt,
                            const float* __restrict__ xc,
                            const float* __restrict__ dbc,
                            const float* __restrict__ xz,
                            const float* __restrict__ A_log,
                            const float* __restrict__ Dp,
                            float* __restrict__ y) {
    int gidx = blockIdx.x * (blockDim.x >> 4) + (threadIdx.x >> 4);
    int s = threadIdx.x & 15;
    int b = gidx / DI, d = gidx % DI;
    if (b >= BB) return;
    float Aval = -__expf(A_log[d * DS + s]);
    float Dv = Dp[d];
    float h = 0.f;

    size_t row0 = (size_t)b * LL;
    float c_dt = dt[row0 * DI + d];
    float c_x  = xc[row0 * DI + d];
    float c_B  = dbc[row0 * DBC_W + DTR + s];
    float c_C  = dbc[row0 * DBC_W + DTR + DS + s];
    float c_z  = xz[row0 * (2 * DI) + DI + d];

    for (int t = 0; t < LL; t++) {
        float n_dt = 0.f, n_x = 0.f, n_B = 0.f, n_C = 0.f, n_z = 0.f;
        if (t + 1 < LL) {
            size_t rn = row0 + t + 1;
            n_dt = dt[rn * DI + d];
            n_x  = xc[rn * DI + d];
            n_B  = dbc[rn * DBC_W + DTR + s];
            n_C  = dbc[rn * DBC_W + DTR + DS + s];
            n_z  = xz[rn * (2 * DI) + DI + d];
        }
        h = __expf(c_dt * Aval) * h + c_dt * c_x * c_B;
        float part = h * c_C;
        #pragma unroll
        for (int off = 8; off; off >>= 1)
            part += __shfl_xor_sync(0xffffffffu, part, off);
        if (s == 0) {
            size_t row = row0 + t;
            y[row * DI + d] = (part + c_x * Dv) * siluf(c_z);
        }
        c_dt = n_dt; c_x = n_x; c_B = n_B; c_C = n_C; c_z = n_z;
    }
}

// ---------------- concat(xf, flip(xbt)) ----------------
__global__ void concat_kernel(const float* __restrict__ xf,
                              const float* __restrict__ xbt,
                              float* __restrict__ cat) {
    int idx = blockIdx.x * blockDim.x + threadIdx.x;
    if (idx >= ROWS * 2 * DD) return;
    int c = idx % (2 * DD);
    int t = (idx / (2 * DD)) % LL;
    int b = idx / (2 * DD * LL);
    float v;
    if (c < DD)
        v = xf[((size_t)(b * LL + t)) * DD + c];
    else
        v = xbt[((size_t)(b * LL + (LL - 1 - t))) * DD + (c - DD)];
    cat[idx] = v;
}

// ---------------- host side ----------------
static float* sym(const void* s) {
    void* p = nullptr;
    cudaGetSymbolAddress(&p, s);
    return (float*)p;
}

template<int ACT, bool FLIPA>
static void launch_tgemm(cudaStream_t st,
                         const float* A, int lda, const float* W, int ldw,
                         float* C, int ldc, int M, int N, int Kd,
                         const float* bias, const float* res, int ldres) {
    static bool attr_set = false;
    if (!attr_set) {
        cudaFuncSetAttribute(tgemm<ACT, FLIPA>, cudaFuncAttributeMaxDynamicSharedMemorySize, SMEM_GEMM);
        attr_set = true;
    }
    dim3 grid((N + GBN - 1) / GBN, (M + GBM - 1) / GBM);
    tgemm<ACT, FLIPA><<<grid, 256, SMEM_GEMM, st>>>(A, lda, W, ldw, C, ldc, M, N, Kd, bias, res, ldres);
}

template<bool FLIPA>
static void run_mamba(cudaStream_t st, const float* xin,
                      const float* in_w, const float* conv_w, const float* conv_b,
                      const float* xproj_w, const float* dt_w, const float* dt_b,
                      const float* A_log, const float* Dp, const float* out_w,
                      float* out,
                      float* xz, float* xc, float* dbc, float* dt, float* y) {
    // in_proj: [4096,768] x [3072,768]^T -> [4096,3072]  (optionally time-flipped A)
    launch_tgemm<0, FLIPA>(st, xin, DD, in_w, DD, xz, 2 * DI, ROWS, 2 * DI, DD, nullptr, nullptr, 0);
    // conv + silu
    conv_silu_kernel<<<(ROWS * DI + 255) / 256, 256, 0, st>>>(xz, conv_w, conv_b, xc);
    // xproj: [4096,1536] x [80,1536]^T -> [4096,80]
    launch_tgemm<0, false>(st, xc, DI, xproj_w, DI, dbc, DBC_W, ROWS, DBC_W, DI, nullptr, nullptr, 0);
    // dt proj + softplus: [4096,48(ld 80)] x [1536,48]^T -> [4096,1536]
    launch_tgemm<2, false>(st, dbc, DBC_W, dt_w, DTR, dt, DI, ROWS, DI, DTR, dt_b, nullptr, 0);
    // scan (fused D skip + silu(z) gating)
    scan_kernel<<<(BB * DI) / 16, 256, 0, st>>>(dt, xc, dbc, xz, A_log, Dp, y);
    // out_proj: [4096,1536] x [768,1536]^T -> [4096,768]
    launch_tgemm<0, false>(st, y, DI, out_w, DI, out, DD, ROWS, DD, DI, nullptr, nullptr, 0);
}

extern "C" void kernel_launch(void* const* d_in, const int* in_sizes, int n_in,
                              void* d_out, int out_size) {
    const float* x        = (const float*)d_in[0];
    const float* norm_g   = (const float*)d_in[1];
    const float* norm_b   = (const float*)d_in[2];
    const float* f_in_w   = (const float*)d_in[3];
    const float* f_conv_w = (const float*)d_in[4];
    const float* f_conv_b = (const float*)d_in[5];
    const float* f_xproj_w= (const float*)d_in[6];
    const float* f_dt_w   = (const float*)d_in[7];
    const float* f_dt_b   = (const float*)d_in[8];
    const float* f_A_log  = (const float*)d_in[9];
    const float* f_D      = (const float*)d_in[10];
    const float* f_out_w  = (const float*)d_in[11];
    const float* b_in_w   = (const float*)d_in[12];
    const float* b_conv_w = (const float*)d_in[13];
    const float* b_conv_b = (const float*)d_in[14];
    const float* b_xproj_w= (const float*)d_in[15];
    const float* b_dt_w   = (const float*)d_in[16];
    const float* b_dt_b   = (const float*)d_in[17];
    const float* b_A_log  = (const float*)d_in[18];
    const float* b_D      = (const float*)d_in[19];
    const float* b_out_w  = (const float*)d_in[20];
    const float* mix_w    = (const float*)d_in[21];
    const float* mix_b    = (const float*)d_in[22];
    const float* ffn_w1   = (const float*)d_in[23];
    const float* ffn_b1   = (const float*)d_in[24];
    const float* ffn_w2   = (const float*)d_in[25];
    const float* ffn_b2   = (const float*)d_in[26];
    const float* ffn_norm_g = (const float*)d_in[27];
    const float* ffn_norm_b = (const float*)d_in[28];

    float* xn    = sym(g_xn);
    float* xz_f  = sym(g_xz_f);
    float* xc_f  = sym(g_xc_f);
    float* dbc_f = sym(g_dbc_f);
    float* dt_f  = sym(g_dt_f);
    float* y_f   = sym(g_y_f);
    float* xz_b  = sym(g_xz_b);
    float* xc_b  = sym(g_xc_b);
    float* dbc_b = sym(g_dbc_b);
    float* dt_b_s= sym(g_dt_b);
    float* y_b   = sym(g_y_b);
    float* xf    = sym(g_xf);
    float* xbt   = sym(g_xbt);
    float* cat   = sym(g_cat);
    float* h     = sym(g_h);
    float* hn    = sym(g_hn);
    float* ff1   = sym(g_ff1);
    float* out   = (float*)d_out;

    // one-time stream/event creation (first call is the uncaptured correctness run)
    static cudaStream_t s2 = nullptr;
    static cudaEvent_t evFork = nullptr, evJoin = nullptr;
    if (!s2) {
        cudaStreamCreateWithFlags(&s2, cudaStreamNonBlocking);
        cudaEventCreateWithFlags(&evFork, cudaEventDisableTiming);
        cudaEventCreateWithFlags(&evJoin, cudaEventDisableTiming);
    }

    // 1) layernorm
    layernorm_kernel<<<ROWS, 256>>>(x, norm_g, norm_b, xn);

    // fork: bwd branch runs on s2 concurrently with fwd on the main stream
    cudaEventRecord(evFork, 0);
    cudaStreamWaitEvent(s2, evFork, 0);

    // 2) forward mamba (main stream)
    run_mamba<false>(0, xn, f_in_w, f_conv_w, f_conv_b, f_xproj_w, f_dt_w, f_dt_b,
                     f_A_log, f_D, f_out_w, xf, xz_f, xc_f, dbc_f, dt_f, y_f);

    // 3) backward mamba on time-flipped input (flip folded into in_proj A-load)
    run_mamba<true>(s2, xn, b_in_w, b_conv_w, b_conv_b, b_xproj_w, b_dt_w, b_dt_b,
                    b_A_log, b_D, b_out_w, xbt, xz_b, xc_b, dbc_b, dt_b_s, y_b);

    // join
    cudaEventRecord(evJoin, s2);
    cudaStreamWaitEvent(0, evJoin, 0);

    // 4) concat (un-flips backward branch)
    concat_kernel<<<(ROWS * 2 * DD + 255) / 256, 256>>>(xf, xbt, cat);

    // 5) mix + bias + residual -> h
    launch_tgemm<0, false>(0, cat, 2 * DD, mix_w, 2 * DD, h, DD, ROWS, DD, 2 * DD, mix_b, x, DD);

    // 6) layernorm 2
    layernorm_kernel<<<ROWS, 256>>>(h, ffn_norm_g, ffn_norm_b, hn);

    // 7) FFN1 + bias + gelu
    launch_tgemm<1, false>(0, hn, DD, ffn_w1, DD, ff1, 4 * DD, ROWS, 4 * DD, DD, ffn_b1, nullptr, 0);

    // 8) FFN2 + bias + residual(h) -> out
    launch_tgemm<0, false>(0, ff1, 4 * DD, ffn_w2, 4 * DD, out, DD, ROWS, DD, 4 * DD, ffn_b2, h, DD);
}

// round 5
// speedup vs baseline: 4.1770x; 1.0706x over previous
#include <cuda_runtime.h>
#include <cuda_bf16.h>
#include <cstdint>

// Problem constants
#define BB 2
#define LL 2048
#define DD 768
#define DI 1536
#define DS 16
#define DTR 48
#define KK 4
#define ROWS (BB*LL)            // 4096
#define DBC_W (DTR + 2*DS)      // 80

// ---------------- scratch (device globals; allocation-free) ----------------
__device__ float g_xn   [ROWS*DD];
__device__ float g_xz_f [(size_t)ROWS*2*DI];
__device__ float g_xc_f [(size_t)ROWS*DI];
__device__ float g_dbc_f[(size_t)ROWS*DBC_W];
__device__ float g_dt_f [(size_t)ROWS*DI];
__device__ float g_y_f  [(size_t)ROWS*DI];
__device__ float g_xz_b [(size_t)ROWS*2*DI];
__device__ float g_xc_b [(size_t)ROWS*DI];
__device__ float g_dbc_b[(size_t)ROWS*DBC_W];
__device__ float g_dt_b [(size_t)ROWS*DI];
__device__ float g_y_b  [(size_t)ROWS*DI];
__device__ float g_xf   [ROWS*DD];
__device__ float g_xb   [ROWS*DD];
__device__ float g_h    [ROWS*DD];
__device__ float g_hn   [ROWS*DD];
__device__ float g_ff1  [(size_t)ROWS*4*DD];

// ---------------- helpers ----------------
__device__ __forceinline__ float siluf(float x) {
    return x / (1.0f + __expf(-x));
}
__device__ __forceinline__ float geluf(float x) {
    float x3 = x * x * x;
    return 0.5f * x * (1.0f + tanhf(0.7978845608028654f * (x + 0.044715f * x3)));
}
__device__ __forceinline__ float softplusf(float x) {
    if (x > 20.0f) return x;
    return log1pf(__expf(x));
}

__device__ __forceinline__ void cpa16(uint32_t dst, const float* src, bool v) {
    int sz = v ? 16 : 0;
    asm volatile("cp.async.cg.shared.global [%0], [%1], 16, %2;"
        :: "r"(dst), "l"(src), "r"(sz) : "memory");
}
#define CP_COMMIT() asm volatile("cp.async.commit_group;" ::: "memory")
#define CP_WAIT(n)  asm volatile("cp.async.wait_group %0;" :: "n"(n) : "memory")

__device__ __forceinline__ uint32_t smem_u32(const void* p) {
    uint32_t a;
    asm("{ .reg .u64 t; cvta.to.shared.u64 t, %1; cvt.u32.u64 %0, t; }" : "=r"(a) : "l"(p));
    return a;
}
__device__ __forceinline__ uint32_t to_tf32(float x) {
    uint32_t u;
    asm("cvt.rna.tf32.f32 %0, %1;" : "=r"(u) : "f"(x));
    return u;
}
__device__ __forceinline__ void mma_tf32(float* d, const uint32_t* a, const uint32_t* b) {
    asm volatile("mma.sync.aligned.m16n8k8.row.col.f32.tf32.tf32.f32 "
                 "{%0,%1,%2,%3}, {%4,%5,%6,%7}, {%8,%9}, {%0,%1,%2,%3};"
                 : "+f"(d[0]), "+f"(d[1]), "+f"(d[2]), "+f"(d[3])
                 : "r"(a[0]), "r"(a[1]), "r"(a[2]), "r"(a[3]),
                   "r"(b[0]), "r"(b[1]));
}

// ================= tf32 mma.sync GEMM =================
// C[m,n] = act(sum_k A[m,k]*W[n,k] + bias[n]) + res[m,n]
// CAT: A columns [0,DD) come from A, [DD,2*DD) from A2 (fused concat).
#define GBM 128
#define GBN 128
#define GBK 32
#define GAS 36                 // padded k-stride (floats)
#define BUFA_BYTES (GBM*GAS*4) // 18432
#define SMEM_GEMM (4*BUFA_BYTES)  // 73728: A[2] + B[2]

template<int ACT, bool CAT>  // ACT: 0=none, 1=gelu, 2=softplus
__global__ __launch_bounds__(256, 2)
void tgemm(const float* __restrict__ A, const float* __restrict__ A2, int lda,
           const float* __restrict__ W, int ldw,
           float* __restrict__ C, int ldc,
           int M, int N, int Kd,
           const float* __restrict__ bias,
           const float* __restrict__ res, int ldres) {
    extern __shared__ float smf[];
    float* As = smf;                    // [2][GBM][GAS]
    float* Bs = smf + 2 * GBM * GAS;    // [2][GBN][GAS]
    uint32_t sA = smem_u32(As);
    uint32_t sB = smem_u32(Bs);

    int tid = threadIdx.x;
    int lane = tid & 31, wid = tid >> 5;
    int bm = blockIdx.y * GBM, bn = blockIdx.x * GBN;
    int wm = (wid & 1) * 64, wn = (wid >> 1) * 32;
    int g = lane >> 2, l = lane & 3;

    float acc[4][4][4];
    #pragma unroll
    for (int f = 0; f < 4; f++)
        #pragma unroll
        for (int j = 0; j < 4; j++)
            #pragma unroll
            for (int c = 0; c < 4; c++) acc[f][j][c] = 0.f;

    const int lr = tid >> 3;        // 0..31
    const int lc = (tid & 7) * 4;   // 0,4,..,28

    auto load_stage = [&](int buf, int kt) {
        int k = kt * GBK + lc;
        bool kok = (k < Kd);
        int kk = kok ? k : 0;
        const float* srcA = A;
        int kcol = kk;
        if (CAT && kk >= DD) { srcA = A2; kcol = kk - DD; }
        #pragma unroll
        for (int j = 0; j < 4; j++) {
            int r = lr + j * 32;
            int gm = bm + r;
            bool v = kok && (gm < M);
            cpa16(sA + buf * BUFA_BYTES + (r * GAS + lc) * 4,
                  srcA + (size_t)(v ? gm : 0) * lda + kcol, v);
        }
        #pragma unroll
        for (int j = 0; j < 4; j++) {
            int r = lr + j * 32;
            int gn = bn + r;
            bool v = kok && (gn < N);
            cpa16(sB + buf * BUFA_BYTES + (r * GAS + lc) * 4,
                  W + (size_t)(v ? gn : 0) * ldw + kk, v);
        }
        CP_COMMIT();
    };

    const int NT = (Kd + GBK - 1) / GBK;
    load_stage(0, 0);

    for (int kt = 0; kt < NT; kt++) {
        int buf = kt & 1;
        if (kt + 1 < NT) {
            load_stage(buf ^ 1, kt + 1);
            CP_WAIT(1);
        } else {
            CP_WAIT(0);
        }
        __syncthreads();

        const float* as = As + buf * GBM * GAS;
        const float* bs = Bs + buf * GBN * GAS;
        #pragma unroll
        for (int k0 = 0; k0 < GBK; k0 += 8) {
            uint32_t af[4][4], bf[4][2];
            #pragma unroll
            for (int f = 0; f < 4; f++) {
                int r0 = wm + f * 16 + g;
                af[f][0] = to_tf32(as[r0 * GAS + k0 + l]);
                af[f][1] = to_tf32(as[(r0 + 8) * GAS + k0 + l]);
                af[f][2] = to_tf32(as[r0 * GAS + k0 + l + 4]);
                af[f][3] = to_tf32(as[(r0 + 8) * GAS + k0 + l + 4]);
            }
            #pragma unroll
            for (int j = 0; j < 4; j++) {
                int c0 = wn + j * 8 + g;
                bf[j][0] = to_tf32(bs[c0 * GAS + k0 + l]);
                bf[j][1] = to_tf32(bs[c0 * GAS + k0 + l + 4]);
            }
            #pragma unroll
            for (int f = 0; f < 4; f++)
                #pragma unroll
                for (int j = 0; j < 4; j++)
                    mma_tf32(acc[f][j], af[f], bf[j]);
        }
        __syncthreads();
    }

    // epilogue: c0:(g,2l) c1:(g,2l+1) c2:(g+8,2l) c3:(g+8,2l+1)
    #pragma unroll
    for (int f = 0; f < 4; f++) {
        int gm0 = bm + wm + f * 16 + g;
        #pragma unroll
        for (int j = 0; j < 4; j++) {
            int gn = bn + wn + j * 8 + 2 * l;
            if (gn >= N) continue;
            bool n1 = (gn + 1 < N);
            float b0 = bias ? bias[gn] : 0.f;
            float b1 = (bias && n1) ? bias[gn + 1] : 0.f;
            #pragma unroll
            for (int half = 0; half < 2; half++) {
                int gm = gm0 + half * 8;
                if (gm >= M) continue;
                float v0 = acc[f][j][half * 2 + 0] + b0;
                float v1 = acc[f][j][half * 2 + 1] + b1;
                if (ACT == 1) { v0 = geluf(v0); v1 = geluf(v1); }
                else if (ACT == 2) { v0 = softplusf(v0); v1 = softplusf(v1); }
                if (res) {
                    v0 += res[(size_t)gm * ldres + gn];
                    if (n1) v1 += res[(size_t)gm * ldres + gn + 1];
                }
                C[(size_t)gm * ldc + gn] = v0;
                if (n1) C[(size_t)gm * ldc + gn + 1] = v1;
            }
        }
    }
}

// ---------------- LayerNorm ----------------
__global__ void layernorm_kernel(const float* __restrict__ x,
                                 const float* __restrict__ g,
                                 const float* __restrict__ b,
                                 float* __restrict__ out) {
    int row = blockIdx.x;
    const float* xr = x + (size_t)row * DD;
    float s = 0.f, s2 = 0.f;
    for (int i = threadIdx.x; i < DD; i += blockDim.x) {
        float v = xr[i];
        s += v; s2 += v * v;
    }
    __shared__ float shm[2][33];
    #pragma unroll
    for (int off = 16; off; off >>= 1) {
        s  += __shfl_xor_sync(0xffffffffu, s,  off);
        s2 += __shfl_xor_sync(0xffffffffu, s2, off);
    }
    int lane = threadIdx.x & 31, w = threadIdx.x >> 5;
    if (lane == 0) { shm[0][w] = s; shm[1][w] = s2; }
    __syncthreads();
    int nw = blockDim.x >> 5;
    if (w == 0) {
        s  = (lane < nw) ? shm[0][lane] : 0.f;
        s2 = (lane < nw) ? shm[1][lane] : 0.f;
        #pragma unroll
        for (int off = 16; off; off >>= 1) {
            s  += __shfl_xor_sync(0xffffffffu, s,  off);
            s2 += __shfl_xor_sync(0xffffffffu, s2, off);
        }
        if (lane == 0) { shm[0][32] = s; shm[1][32] = s2; }
    }
    __syncthreads();
    float mu  = shm[0][32] * (1.0f / DD);
    float var = shm[1][32] * (1.0f / DD) - mu * mu;
    float inv = rsqrtf(var + 1e-5f);
    float* orow = out + (size_t)row * DD;
    for (int i = threadIdx.x; i < DD; i += blockDim.x)
        orow[i] = (xr[i] - mu) * inv * g[i] + b[i];
}

// ---------------- causal conv (K=4) + bias + silu, direction-aware ----------------
// DIR=+1: taps at t-3..t (standard causal). DIR=-1: equivalent of running the
// causal conv on the time-flipped sequence, expressed on unflipped data:
// taps at t+3-k with weight w[k], zero beyond the sequence end.
template<int DIR>
__global__ void conv_silu_kernel(const float* __restrict__ xz,
                                 const float* __restrict__ cw,
                                 const float* __restrict__ cb,
                                 float* __restrict__ out) {
    int idx = blockIdx.x * blockDim.x + threadIdx.x;
    if (idx >= ROWS * DI) return;
    int d = idx % DI;
    int t = (idx / DI) % LL;
    int b = idx / (DI * LL);
    float acc = cb[d];
    #pragma unroll
    for (int k = 0; k < KK; k++) {
        int tt = (DIR > 0) ? (t - (KK - 1) + k) : (t + (KK - 1) - k);
        if (tt >= 0 && tt < LL)
            acc += xz[((size_t)(b * LL + tt)) * (2 * DI) + d] * cw[d * KK + k];
    }
    out[idx] = siluf(acc);
}

// ---------------- selective scan + D skip + z-gating ----------------
// Direction-aware (DIR=-1 scans time in reverse on unflipped data), with
// 4-step chunked double-buffered prefetch to amortize L2 latency.
template<int DIR>
__global__ void scan_kernel(const float* __restrict__ dt,
                            const float* __restrict__ xc,
                            const float* __restrict__ dbc,
                            const float* __restrict__ xz,
                            const float* __restrict__ A_log,
                            const float* __restrict__ Dp,
                            float* __restrict__ y) {
    int gidx = blockIdx.x * (blockDim.x >> 4) + (threadIdx.x >> 4);
    int s = threadIdx.x & 15;
    int b = gidx / DI, d = gidx % DI;
    if (b >= BB) return;
    float Aval = -__expf(A_log[d * DS + s]);
    float Dv = Dp[d];
    float h = 0.f;
    size_t base = (size_t)b * LL;

    const int CH = 4;
    // buf[pb][field][i]: 0=dt 1=x 2=B 3=C 4=z
    float buf[2][5][CH];

    auto loadch = [&](int u0, int pb) {
        #pragma unroll
        for (int i = 0; i < CH; i++) {
            int u = u0 + i;
            int t = (DIR > 0) ? u : (LL - 1 - u);
            size_t row = base + t;
            buf[pb][0][i] = dt[row * DI + d];
            buf[pb][1][i] = xc[row * DI + d];
            buf[pb][2][i] = dbc[row * DBC_W + DTR + s];
            buf[pb][3][i] = dbc[row * DBC_W + DTR + DS + s];
            buf[pb][4][i] = xz[row * (2 * DI) + DI + d];
        }
    };

    loadch(0, 0);
    for (int u0 = 0; u0 < LL; u0 += CH) {
        int pb = (u0 / CH) & 1;
        if (u0 + CH < LL) loadch(u0 + CH, pb ^ 1);
        float e[CH];
        #pragma unroll
        for (int i = 0; i < CH; i++)
            e[i] = __expf(buf[pb][0][i] * Aval);
        #pragma unroll
        for (int i = 0; i < CH; i++) {
            h = e[i] * h + buf[pb][0][i] * buf[pb][1][i] * buf[pb][2][i];
            float part = h * buf[pb][3][i];
            #pragma unroll
            for (int off = 8; off; off >>= 1)
                part += __shfl_xor_sync(0xffffffffu, part, off);
            if (s == 0) {
                int u = u0 + i;
                int t = (DIR > 0) ? u : (LL - 1 - u);
                size_t row = base + t;
                y[row * DI + d] = (part + buf[pb][1][i] * Dv) * siluf(buf[pb][4][i]);
            }
        }
    }
}

// ---------------- host side ----------------
static float* sym(const void* s) {
    void* p = nullptr;
    cudaGetSymbolAddress(&p, s);
    return (float*)p;
}

template<int ACT, bool CAT>
static void launch_tgemm(cudaStream_t st,
                         const float* A, const float* A2, int lda,
                         const float* W, int ldw,
                         float* C, int ldc, int M, int N, int Kd,
                         const float* bias, const float* res, int ldres) {
    static bool attr_set = false;
    if (!attr_set) {
        cudaFuncSetAttribute(tgemm<ACT, CAT>, cudaFuncAttributeMaxDynamicSharedMemorySize, SMEM_GEMM);
        attr_set = true;
    }
    dim3 grid((N + GBN - 1) / GBN, (M + GBM - 1) / GBM);
    tgemm<ACT, CAT><<<grid, 256, SMEM_GEMM, st>>>(A, A2, lda, W, ldw, C, ldc, M, N, Kd, bias, res, ldres);
}

template<int DIR>
static void run_mamba(cudaStream_t st, const float* xin,
                      const float* in_w, const float* conv_w, const float* conv_b,
                      const float* xproj_w, const float* dt_w, const float* dt_b,
                      const float* A_log, const float* Dp, const float* out_w,
                      float* out,
                      float* xz, float* xc, float* dbc, float* dt, float* y) {
    // in_proj: [4096,768] x [3072,768]^T -> [4096,3072]
    launch_tgemm<0, false>(st, xin, nullptr, DD, in_w, DD, xz, 2 * DI, ROWS, 2 * DI, DD, nullptr, nullptr, 0);
    // conv + silu (direction-aware)
    conv_silu_kernel<DIR><<<(ROWS * DI + 255) / 256, 256, 0, st>>>(xz, conv_w, conv_b, xc);
    // xproj: [4096,1536] x [80,1536]^T -> [4096,80]
    launch_tgemm<0, false>(st, xc, nullptr, DI, xproj_w, DI, dbc, DBC_W, ROWS, DBC_W, DI, nullptr, nullptr, 0);
    // dt proj + softplus
    launch_tgemm<2, false>(st, dbc, nullptr, DBC_W, dt_w, DTR, dt, DI, ROWS, DI, DTR, dt_b, nullptr, 0);
    // scan (direction-aware, fused D skip + silu(z) gating)
    scan_kernel<DIR><<<(BB * DI) / 16, 256, 0, st>>>(dt, xc, dbc, xz, A_log, Dp, y);
    // out_proj: [4096,1536] x [768,1536]^T -> [4096,768]
    launch_tgemm<0, false>(st, y, nullptr, DI, out_w, DI, out, DD, ROWS, DD, DI, nullptr, nullptr, 0);
}

extern "C" void kernel_launch(void* const* d_in, const int* in_sizes, int n_in,
                              void* d_out, int out_size) {
    const float* x        = (const float*)d_in[0];
    const float* norm_g   = (const float*)d_in[1];
    const float* norm_b   = (const float*)d_in[2];
    const float* f_in_w   = (const float*)d_in[3];
    const float* f_conv_w = (const float*)d_in[4];
    const float* f_conv_b = (const float*)d_in[5];
    const float* f_xproj_w= (const float*)d_in[6];
    const float* f_dt_w   = (const float*)d_in[7];
    const float* f_dt_b   = (const float*)d_in[8];
    const float* f_A_log  = (const float*)d_in[9];
    const float* f_D      = (const float*)d_in[10];
    const float* f_out_w  = (const float*)d_in[11];
    const float* b_in_w   = (const float*)d_in[12];
    const float* b_conv_w = (const float*)d_in[13];
    const float* b_conv_b = (const float*)d_in[14];
    const float* b_xproj_w= (const float*)d_in[15];
    const float* b_dt_w   = (const float*)d_in[16];
    const float* b_dt_b   = (const float*)d_in[17];
    const float* b_A_log  = (const float*)d_in[18];
    const float* b_D      = (const float*)d_in[19];
    const float* b_out_w  = (const float*)d_in[20];
    const float* mix_w    = (const float*)d_in[21];
    const float* mix_b    = (const float*)d_in[22];
    const float* ffn_w1   = (const float*)d_in[23];
    const float* ffn_b1   = (const float*)d_in[24];
    const float* ffn_w2   = (const float*)d_in[25];
    const float* ffn_b2   = (const float*)d_in[26];
    const float* ffn_norm_g = (const float*)d_in[27];
    const float* ffn_norm_b = (const float*)d_in[28];

    float* xn    = sym(g_xn);
    float* xz_f  = sym(g_xz_f);
    float* xc_f  = sym(g_xc_f);
    float* dbc_f = sym(g_dbc_f);
    float* dt_f  = sym(g_dt_f);
    float* y_f   = sym(g_y_f);
    float* xz_b  = sym(g_xz_b);
    float* xc_b  = sym(g_xc_b);
    float* dbc_b = sym(g_dbc_b);
    float* dt_b_s= sym(g_dt_b);
    float* y_b   = sym(g_y_b);
    float* xf    = sym(g_xf);
    float* xb    = sym(g_xb);
    float* h     = sym(g_h);
    float* hn    = sym(g_hn);
    float* ff1   = sym(g_ff1);
    float* out   = (float*)d_out;

    static cudaStream_t s2 = nullptr;
    static cudaEvent_t evFork = nullptr, evJoin = nullptr;
    if (!s2) {
        cudaStreamCreateWithFlags(&s2, cudaStreamNonBlocking);
        cudaEventCreateWithFlags(&evFork, cudaEventDisableTiming);
        cudaEventCreateWithFlags(&evJoin, cudaEventDisableTiming);
    }

    // 1) layernorm
    layernorm_kernel<<<ROWS, 256>>>(x, norm_g, norm_b, xn);

    // fork: bwd branch on s2 concurrent with fwd on main stream
    cudaEventRecord(evFork, 0);
    cudaStreamWaitEvent(s2, evFork, 0);

    // 2) forward mamba
    run_mamba<1>(0, xn, f_in_w, f_conv_w, f_conv_b, f_xproj_w, f_dt_w, f_dt_b,
                 f_A_log, f_D, f_out_w, xf, xz_f, xc_f, dbc_f, dt_f, y_f);

    // 3) backward mamba: direction-aware, no data flips anywhere
    run_mamba<-1>(s2, xn, b_in_w, b_conv_w, b_conv_b, b_xproj_w, b_dt_w, b_dt_b,
                  b_A_log, b_D, b_out_w, xb, xz_b, xc_b, dbc_b, dt_b_s, y_b);

    // join
    cudaEventRecord(evJoin, s2);
    cudaStreamWaitEvent(0, evJoin, 0);

    // 4+5) concat fused into mix GEMM + bias + residual -> h
    launch_tgemm<0, true>(0, xf, xb, DD, mix_w, 2 * DD, h, DD, ROWS, DD, 2 * DD, mix_b, x, DD);

    // 6) layernorm 2
    layernorm_kernel<<<ROWS, 256>>>(h, ffn_norm_g, ffn_norm_b, hn);

    // 7) FFN1 + bias + gelu
    launch_tgemm<1, false>(0, hn, nullptr, DD, ffn_w1, DD, ff1, 4 * DD, ROWS, 4 * DD, DD, ffn_b1, nullptr, 0);

    // 8) FFN2 + bias + residual(h) -> out
    launch_tgemm<0, false>(0, ff1, nullptr, 4 * DD, ffn_w2, 4 * DD, out, DD, ROWS, DD, 4 * DD, ffn_b2, h, DD);
}